// round 10
// baseline (speedup 1.0000x reference)
#include <cuda_runtime.h>
#include <cuda_fp16.h>

#define NB   32
#define CIN  240
#define HH   56
#define WW   56
#define HW   3136
#define MID  120
#define COUT 480
#define GRP  3
#define GIN  80    // Cin / G
#define GMID 40    // mid / G
#define GOUT 160   // Cout / G

// Scratch (allocation-free rule: __device__ globals)
__device__ __half   g_y1h[NB * MID * HW];       // conv1 output (post BN+ReLU), fp16 planar
__device__ unsigned g_xh[NB * 120 * HW];        // x as k-pair-packed half2 words [n][kk<120][px]
__device__ unsigned g_y2h[NB * 72 * HW];        // dw out, SHUFFLED, packed half2, 24 kk-rows/group (20 used + 4 zero)
// Pre-packed fp16 A-fragments (mma.m16n8k16 per-lane layout), BN scale FOLDED IN
__device__ uint4 g_wscf[14400];   // wsc*scale_sc: [ct3][kc5][kt3][mt10][lane32]
__device__ uint4 g_w3f[2880];     // w3*scale3:    [ct3][kt3][mt10][lane32] (K 40->48 zero-pad)
__device__ uint4 g_w1f[1440];     // w1*scale1:    [g3][kt5][mt3][lane32]  (M 40->48 zero-pad)

static __device__ __forceinline__ unsigned pack_h2(float lo, float hi) {
    __half2 h = __floats2half2_rn(lo, hi);
    return *reinterpret_cast<unsigned*>(&h);
}

static __device__ __forceinline__ void mma_f16(float c[4], const unsigned a[4],
                                               const unsigned b[2]) {
    asm volatile(
        "mma.sync.aligned.m16n8k16.row.col.f32.f16.f16.f32 "
        "{%0,%1,%2,%3}, {%4,%5,%6,%7}, {%8,%9}, {%0,%1,%2,%3};"
        : "+f"(c[0]), "+f"(c[1]), "+f"(c[2]), "+f"(c[3])
        : "r"(a[0]), "r"(a[1]), "r"(a[2]), "r"(a[3]), "r"(b[0]), "r"(b[1]));
}

static __device__ __forceinline__ unsigned smem_u32(const void* p) {
    return (unsigned)__cvta_generic_to_shared(p);
}
#define CP16(dst, src) \
    asm volatile("cp.async.cg.shared.global [%0], [%1], 16;" :: "r"(dst), "l"(src))
#define CP_COMMIT() asm volatile("cp.async.commit_group;")
#define CP_WAIT0()  asm volatile("cp.async.wait_group 0;")

// ---------------------------------------------------------------------------
// prep_w: pack wsc/w3/w1 into per-lane fp16 m16n8k16 A-fragments, scales folded.
// ---------------------------------------------------------------------------
__global__ void prep_w(const float* __restrict__ wsc, const float* __restrict__ w3,
                       const float* __restrict__ w1,
                       const float* __restrict__ scale_sc, const float* __restrict__ scale3,
                       const float* __restrict__ scale1)
{
    int idx = blockIdx.x * 256 + threadIdx.x;
    if (idx < 14400) {
        int lane = idx & 31; int r = idx >> 5;
        int mt = r % 10; r /= 10;
        int kt = r % 3;  r /= 3;
        int kc = r % 5;  int ct = r / 5;
        int gid = lane >> 2, tig = lane & 3;
        int row = ct * GOUT + mt * 16 + gid;
        int c0 = kc * 48 + kt * 16 + 2 * tig;
        int c2 = c0 + 8;
        float sa = scale_sc[row], sb = scale_sc[row + 8];
        const float* wr0 = wsc + (size_t)row * CIN;
        const float* wr8 = wsc + (size_t)(row + 8) * CIN;
        uint4 v;
        v.x = pack_h2(wr0[c0] * sa, wr0[c0 + 1] * sa);
        v.y = pack_h2(wr8[c0] * sb, wr8[c0 + 1] * sb);
        v.z = pack_h2(wr0[c2] * sa, wr0[c2 + 1] * sa);
        v.w = pack_h2(wr8[c2] * sb, wr8[c2 + 1] * sb);
        g_wscf[idx] = v;
    } else if (idx < 14400 + 2880) {
        int i2 = idx - 14400;
        int lane = i2 & 31; int r = i2 >> 5;
        int mt = r % 10; r /= 10;
        int kt = r % 3;  int ct = r / 3;
        int gid = lane >> 2, tig = lane & 3;
        int row = ct * GOUT + mt * 16 + gid;
        int c0 = kt * 16 + 2 * tig;
        int c2 = c0 + 8;
        float sa = scale3[row], sb = scale3[row + 8];
        const float* wr0 = w3 + (size_t)row * GMID;
        const float* wr8 = w3 + (size_t)(row + 8) * GMID;
        float e00 = (c0     < GMID) ? wr0[c0]     : 0.f;
        float e01 = (c0 + 1 < GMID) ? wr0[c0 + 1] : 0.f;
        float e80 = (c0     < GMID) ? wr8[c0]     : 0.f;
        float e81 = (c0 + 1 < GMID) ? wr8[c0 + 1] : 0.f;
        float f00 = (c2     < GMID) ? wr0[c2]     : 0.f;
        float f01 = (c2 + 1 < GMID) ? wr0[c2 + 1] : 0.f;
        float f80 = (c2     < GMID) ? wr8[c2]     : 0.f;
        float f81 = (c2 + 1 < GMID) ? wr8[c2 + 1] : 0.f;
        uint4 v;
        v.x = pack_h2(e00 * sa, e01 * sa);
        v.y = pack_h2(e80 * sb, e81 * sb);
        v.z = pack_h2(f00 * sa, f01 * sa);
        v.w = pack_h2(f80 * sb, f81 * sb);
        g_w3f[i2] = v;
    } else if (idx < 14400 + 2880 + 1440) {
        int i3 = idx - 14400 - 2880;
        int lane = i3 & 31; int r = i3 >> 5;
        int mt = r % 3; r /= 3;
        int kt = r % 5; int g = r / 5;
        int gid = lane >> 2, tig = lane & 3;
        int r0 = mt * 16 + gid;
        int r1 = r0 + 8;
        int c0 = kt * 16 + 2 * tig;
        int c2 = c0 + 8;
        float sa = (r0 < GMID) ? scale1[g * GMID + r0] : 0.f;
        float sb = (r1 < GMID) ? scale1[g * GMID + r1] : 0.f;
        const float* wr0 = w1 + ((size_t)g * GMID + r0) * GIN;
        const float* wr8 = w1 + ((size_t)g * GMID + r1) * GIN;
        uint4 v;
        v.x = pack_h2((r0 < GMID) ? wr0[c0] * sa : 0.f, (r0 < GMID) ? wr0[c0 + 1] * sa : 0.f);
        v.y = pack_h2((r1 < GMID) ? wr8[c0] * sb : 0.f, (r1 < GMID) ? wr8[c0 + 1] * sb : 0.f);
        v.z = pack_h2((r0 < GMID) ? wr0[c2] * sa : 0.f, (r0 < GMID) ? wr0[c2 + 1] * sa : 0.f);
        v.w = pack_h2((r1 < GMID) ? wr8[c2] * sb : 0.f, (r1 < GMID) ? wr8[c2 + 1] * sb : 0.f);
        g_w1f[i3] = v;
    }
}

// ---------------------------------------------------------------------------
// prep_x: convert x to fp16, packing adjacent k-pairs into half2 words.
// ---------------------------------------------------------------------------
__global__ __launch_bounds__(256) void prep_x(const float* __restrict__ x)
{
    int idx = blockIdx.x * 256 + threadIdx.x;    // NB*120*784 exactly
    int q  = idx % 784;
    int r  = idx / 784;
    int kk = r % 120, n = r / 120;
    const float4* r0 = reinterpret_cast<const float4*>(x) + ((size_t)n * CIN + 2 * kk) * 784 + q;
    const float4* r1 = r0 + 784;
    float4 a = *r0, b = *r1;
    uint4 o;
    o.x = pack_h2(a.x, b.x);
    o.y = pack_h2(a.y, b.y);
    o.z = pack_h2(a.z, b.z);
    o.w = pack_h2(a.w, b.w);
    reinterpret_cast<uint4*>(g_xh)[((size_t)n * 120 + kk) * 784 + q] = o;
}

// ---------------------------------------------------------------------------
// zero_pad: zero the 4 padded kk-rows per group in g_y2h.
// ---------------------------------------------------------------------------
__global__ __launch_bounds__(256) void zero_pad()
{
    int idx = blockIdx.x * 256 + threadIdx.x;    // NB*12*784 exactly
    int q = idx % 784;
    int r = (idx / 784) % 12;
    int n = idx / (784 * 12);
    int kk = (r >> 2) * 24 + 20 + (r & 3);
    reinterpret_cast<uint4*>(g_y2h)[((size_t)n * 72 + kk) * 784 + q] = make_uint4(0, 0, 0, 0);
}

// ---------------------------------------------------------------------------
// K1 (MMA): grouped 1x1 conv + BN(+scale folded) + ReLU -> g_y1h (fp16)
// M=48 (40 valid), K=80 (5 kt), N=64 px. grid (49, 3, 32), 128 thr.
// ---------------------------------------------------------------------------
#define BROW1 72
__global__ __launch_bounds__(128) void k1_mma(const float* __restrict__ shift1)
{
    const int tile = blockIdx.x, g = blockIdx.y, n = blockIdx.z;
    const int tid = threadIdx.x, lane = tid & 31, wn = tid >> 5;
    const int gid = lane >> 2, tig = lane & 3;

    __shared__ __align__(16) uint4    s_a[480];          // 5kt x 3mt x 32
    __shared__ __align__(16) unsigned s_B[40 * BROW1];   // 40 kk-rows x 64 (+8 pad)

    {
        unsigned d = smem_u32(s_a);
        const uint4* src = g_w1f + (size_t)g * 480;
        #pragma unroll
        for (int i = tid; i < 480; i += 128)
            CP16(d + i * 16, src + i);
    }
    {
        unsigned d = smem_u32(s_B);
        const unsigned* src = g_xh + ((size_t)n * 120 + g * 40) * HW + tile * 64;
        #pragma unroll
        for (int i = tid; i < 640; i += 128) {
            int row = i >> 4, c4 = i & 15;
            CP16(d + row * (BROW1 * 4) + c4 * 16, src + (size_t)row * HW + c4 * 4);
        }
    }
    CP_COMMIT();
    CP_WAIT0();
    __syncthreads();

    float acc[3][2][4];
    #pragma unroll
    for (int mt = 0; mt < 3; mt++)
        #pragma unroll
        for (int t = 0; t < 2; t++)
            #pragma unroll
            for (int c = 0; c < 4; c++) acc[mt][t][c] = 0.f;

    #pragma unroll
    for (int kt = 0; kt < 5; kt++) {
        unsigned a[3][4];
        #pragma unroll
        for (int mt = 0; mt < 3; mt++)
            *reinterpret_cast<uint4*>(a[mt]) = s_a[(kt * 3 + mt) * 32 + lane];
        unsigned b[2][2];
        const int kb = kt * 8 + tig;
        #pragma unroll
        for (int t = 0; t < 2; t++) {
            int col = wn * 16 + t * 8 + gid;
            b[t][0] = s_B[kb * BROW1 + col];
            b[t][1] = s_B[(kb + 4) * BROW1 + col];
        }
        #pragma unroll
        for (int mt = 0; mt < 3; mt++)
            #pragma unroll
            for (int t = 0; t < 2; t++)
                mma_f16(acc[mt][t], a[mt], b[t]);
    }

    // epilogue: relu(acc + shift1) -> fp16 g_y1h (rows >= 40 discarded)
    #pragma unroll
    for (int mt = 0; mt < 3; mt++) {
        int r0 = mt * 16 + gid;
        int r1 = r0 + 8;
        int m0 = g * GMID + r0;
        float h0 = shift1[m0];
        float h1 = (r1 < GMID) ? shift1[g * GMID + r1] : 0.f;
        #pragma unroll
        for (int t = 0; t < 2; t++) {
            int px = tile * 64 + wn * 16 + t * 8 + 2 * tig;
            __half2 v0 = __floats2half2_rn(fmaxf(acc[mt][t][0] + h0, 0.f),
                                           fmaxf(acc[mt][t][1] + h0, 0.f));
            *reinterpret_cast<__half2*>(g_y1h + ((size_t)n * MID + m0) * HW + px) = v0;
            if (r1 < GMID) {
                __half2 v1 = __floats2half2_rn(fmaxf(acc[mt][t][2] + h1, 0.f),
                                               fmaxf(acc[mt][t][3] + h1, 0.f));
                *reinterpret_cast<__half2*>(g_y1h + ((size_t)n * MID + g * GMID + r1) * HW + px) = v1;
            }
        }
    }
}

// ---------------------------------------------------------------------------
// K2: depthwise 3x3 (pad 1) + BN; reads fp16 y1, two shuffled channels per
// thread, packed half2 write into g_y2h.
// ---------------------------------------------------------------------------
__global__ __launch_bounds__(256) void k2_dw(
    const float* __restrict__ w2, const float* __restrict__ scale2,
    const float* __restrict__ shift2)
{
    int idx = blockIdx.x * 256 + threadIdx.x;   // NB*60*784 threads exactly
    int q  = idx % 784;
    int r  = idx / 784;
    int kk = r % 60, n = r / 60;
    int s0 = 2 * kk, s1 = 2 * kk + 1;
    int m0 = (s0 % 3) * 40 + s0 / 3;
    int m1 = (s1 % 3) * 40 + s1 / 3;
    int w0 = (q * 4) % WW, h = (q * 4) / WW;

    float v[2][4];
    #pragma unroll
    for (int ch = 0; ch < 2; ch++) {
        int m = ch ? m1 : m0;
        const __half* p = g_y1h + ((size_t)n * MID + m) * HW + h * WW + w0;
        float l[3][6];
        #pragma unroll
        for (int rr = 0; rr < 3; rr++) {
            int hh = h - 1 + rr;
            if (hh >= 0 && hh < HH) {
                const __half* pr = p + (rr - 1) * WW;
                __half2 a = *reinterpret_cast<const __half2*>(pr);
                __half2 b = *reinterpret_cast<const __half2*>(pr + 2);
                float2 fa = __half22float2(a), fb = __half22float2(b);
                l[rr][1] = fa.x; l[rr][2] = fa.y; l[rr][3] = fb.x; l[rr][4] = fb.y;
                l[rr][0] = (w0 > 0)      ? __half2float(pr[-1]) : 0.f;
                l[rr][5] = (w0 + 4 < WW) ? __half2float(pr[4])  : 0.f;
            } else {
                #pragma unroll
                for (int j = 0; j < 6; j++) l[rr][j] = 0.f;
            }
        }
        const float* wp = w2 + m * 9;
        float wgt[9];
        #pragma unroll
        for (int i = 0; i < 9; i++) wgt[i] = wp[i];
        float sc = scale2[m], sh = shift2[m];
        #pragma unroll
        for (int j = 0; j < 4; j++) {
            float a = 0.f;
            #pragma unroll
            for (int rr = 0; rr < 3; rr++)
                #pragma unroll
                for (int d = 0; d < 3; d++)
                    a = fmaf(wgt[rr * 3 + d], l[rr][j + d], a);
            v[ch][j] = fmaf(a, sc, sh);
        }
    }

    int row = (s0 / 40) * 24 + (s0 % 40) / 2;
    uint4 o;
    o.x = pack_h2(v[0][0], v[1][0]);
    o.y = pack_h2(v[0][1], v[1][1]);
    o.z = pack_h2(v[0][2], v[1][2]);
    o.w = pack_h2(v[0][3], v[1][3]);
    reinterpret_cast<uint4*>(g_y2h)[((size_t)n * 72 + row) * 784 + q] = o;
}

// ---------------------------------------------------------------------------
// K3: fp16 m16n8k16 MMA. 256 thr, warp grid 2m x 4n, K chunks of 48 (3 kt).
// A frags + B half2 tiles both cp.async double-buffered. 2 CTAs/SM.
// ---------------------------------------------------------------------------
#define AW_ELEMS 960
#define BROW 72
#define BWORDS (24 * BROW)
#define SMEM_K3 (2 * AW_ELEMS * 16 + 2 * BWORDS * 4)

static __device__ __forceinline__ void cp_A(uint4* __restrict__ dst,
                                            const uint4* __restrict__ src, int tid)
{
    unsigned d = smem_u32(dst);
    #pragma unroll
    for (int i = tid; i < AW_ELEMS; i += 256)
        CP16(d + i * 16, src + i);
}

static __device__ __forceinline__ void cp_B(unsigned* __restrict__ dst,
                                            const unsigned* __restrict__ src, int tid)
{
    unsigned d = smem_u32(dst);
    #pragma unroll
    for (int i = tid; i < 384; i += 256) {
        int row = i >> 4, c4 = i & 15;
        CP16(d + row * (BROW * 4) + c4 * 16, src + (size_t)row * HW + c4 * 4);
    }
}

static __device__ __forceinline__ void compute_chunk(
    const uint4* __restrict__ aw, const unsigned* __restrict__ sB,
    int wm, int wn, int lane, float acc[5][2][4])
{
    const int gid = lane >> 2, tig = lane & 3;
    #pragma unroll
    for (int kt = 0; kt < 3; kt++) {
        unsigned a[5][4];
        #pragma unroll
        for (int j = 0; j < 5; j++)
            *reinterpret_cast<uint4*>(a[j]) = aw[(kt * 10 + wm * 5 + j) * 32 + lane];
        unsigned b[2][2];
        const int kb = kt * 8 + tig;
        #pragma unroll
        for (int t = 0; t < 2; t++) {
            int col = wn * 16 + t * 8 + gid;
            b[t][0] = sB[kb * BROW + col];
            b[t][1] = sB[(kb + 4) * BROW + col];
        }
        #pragma unroll
        for (int j = 0; j < 5; j++)
            #pragma unroll
            for (int t = 0; t < 2; t++)
                mma_f16(acc[j][t], a[j], b[t]);
    }
}

__global__ __launch_bounds__(256, 2) void k3_fused(
    const float* __restrict__ shift3, const float* __restrict__ shift_sc,
    float* __restrict__ out)
{
    const int tile = blockIdx.x, ct = blockIdx.y, n = blockIdx.z;
    const int tid = threadIdx.x, lane = tid & 31, warp = tid >> 5;
    const int wm = warp & 1;
    const int wn = warp >> 1;
    const int gid = lane >> 2, tig = lane & 3;

    extern __shared__ __align__(16) char smem[];
    uint4*    s_aw = reinterpret_cast<uint4*>(smem);
    unsigned* s_B  = reinterpret_cast<unsigned*>(smem + 2 * AW_ELEMS * 16);

    float acc[5][2][4];
    #pragma unroll
    for (int j = 0; j < 5; j++)
        #pragma unroll
        for (int t = 0; t < 2; t++)
            #pragma unroll
            for (int c = 0; c < 4; c++) acc[j][t][c] = 0.f;

    const uint4* a_src[6];
    const unsigned* b_src[6];
    a_src[0] = g_w3f + (size_t)ct * 960;
    b_src[0] = g_y2h + ((size_t)n * 72 + ct * 24) * HW + tile * 64;
    #pragma unroll
    for (int kc = 0; kc < 5; kc++) {
        a_src[1 + kc] = g_wscf + (size_t)(ct * 5 + kc) * 960;
        b_src[1 + kc] = g_xh + ((size_t)n * 120 + kc * 24) * HW + tile * 64;
    }

    cp_A(s_aw, a_src[0], tid);
    cp_B(s_B, b_src[0], tid);
    CP_COMMIT();

    #pragma unroll 1
    for (int c = 0; c < 6; c++) {
        int cb = c & 1;
        CP_WAIT0();
        __syncthreads();
        if (c < 5) {
            cp_A(s_aw + ((c + 1) & 1) * AW_ELEMS, a_src[c + 1], tid);
            cp_B(s_B + ((c + 1) & 1) * BWORDS, b_src[c + 1], tid);
            CP_COMMIT();
        }
        compute_chunk(s_aw + cb * AW_ELEMS, s_B + cb * BWORDS, wm, wn, lane, acc);
        if (c == 0) {
            #pragma unroll
            for (int j = 0; j < 5; j++) {
                int rb = ct * GOUT + wm * 80 + j * 16;
                int r0 = rb + gid, r1 = r0 + 8;
                float h3a = shift3[r0], hsa = shift_sc[r0];
                float h3b = shift3[r1], hsb = shift_sc[r1];
                #pragma unroll
                for (int t = 0; t < 2; t++) {
                    acc[j][t][0] = fmaxf(acc[j][t][0] + h3a, 0.f) + hsa;
                    acc[j][t][1] = fmaxf(acc[j][t][1] + h3a, 0.f) + hsa;
                    acc[j][t][2] = fmaxf(acc[j][t][2] + h3b, 0.f) + hsb;
                    acc[j][t][3] = fmaxf(acc[j][t][3] + h3b, 0.f) + hsb;
                }
            }
        }
        __syncthreads();
    }

    #pragma unroll
    for (int j = 0; j < 5; j++) {
        int rb = ct * GOUT + wm * 80 + j * 16;
        int r0 = rb + gid, r1 = r0 + 8;
        #pragma unroll
        for (int t = 0; t < 2; t++) {
            int px = tile * 64 + wn * 16 + t * 8 + 2 * tig;
            float2 v0, v1;
            v0.x = acc[j][t][0]; v0.y = acc[j][t][1];
            v1.x = acc[j][t][2]; v1.y = acc[j][t][3];
            *reinterpret_cast<float2*>(out + ((size_t)n * COUT + r0) * HW + px) = v0;
            *reinterpret_cast<float2*>(out + ((size_t)n * COUT + r1) * HW + px) = v1;
        }
    }
}

// ---------------------------------------------------------------------------
extern "C" void kernel_launch(void* const* d_in, const int* in_sizes, int n_in,
                              void* d_out, int out_size)
{
    const float* x        = (const float*)d_in[0];
    const float* w1       = (const float*)d_in[1];
    const float* scale1   = (const float*)d_in[2];
    const float* shift1   = (const float*)d_in[3];
    const float* w2       = (const float*)d_in[4];
    const float* scale2   = (const float*)d_in[5];
    const float* shift2   = (const float*)d_in[6];
    const float* w3       = (const float*)d_in[7];
    const float* scale3   = (const float*)d_in[8];
    const float* shift3   = (const float*)d_in[9];
    const float* wsc      = (const float*)d_in[10];
    const float* scale_sc = (const float*)d_in[11];
    const float* shift_sc = (const float*)d_in[12];
    float* out = (float*)d_out;

    cudaFuncSetAttribute(k3_fused, cudaFuncAttributeMaxDynamicSharedMemorySize, SMEM_K3);

    prep_w<<<(14400 + 2880 + 1440 + 255) / 256, 256>>>(wsc, w3, w1, scale_sc, scale3, scale1);
    prep_x<<<(NB * 120 * 784) / 256, 256>>>(x);
    zero_pad<<<(NB * 12 * 784) / 256, 256>>>();
    k1_mma<<<dim3(49, 3, NB), 128>>>(shift1);
    k2_dw<<<(NB * 60 * 784) / 256, 256>>>(w2, scale2, shift2);
    k3_fused<<<dim3(49, 3, NB), 256, SMEM_K3>>>(shift3, shift_sc, out);
}

// round 11
// speedup vs baseline: 1.1990x; 1.1990x over previous
#include <cuda_runtime.h>
#include <cuda_fp16.h>

#define NB   32
#define CIN  240
#define HH   56
#define WW   56
#define HW   3136
#define MID  120
#define COUT 480
#define GRP  3
#define GIN  80    // Cin / G
#define GMID 40    // mid / G
#define GOUT 160   // Cout / G

// Scratch (allocation-free rule: __device__ globals)
__device__ __half   g_y1h[NB * MID * HW];       // conv1 output (post BN+ReLU), fp16 planar
__device__ unsigned g_xh[NB * 120 * HW];        // x as k-pair-packed half2 words [n][kk<120][px]
__device__ unsigned g_y2h[NB * 72 * HW];        // dw out, SHUFFLED, packed half2, 24 kk-rows/group (20 used + 4 zero)
// Pre-packed fp16 A-fragments (mma.m16n8k16 per-lane layout), BN scale FOLDED IN
__device__ uint4 g_wscf[14400];   // wsc*scale_sc: [ct3][kc5][kt3][mt10][lane32]
__device__ uint4 g_w3f[2880];     // w3*scale3:    [ct3][kt3][mt10][lane32] (K 40->48 zero-pad)
__device__ uint4 g_w1f[1440];     // w1*scale1:    [g3][kt5][mt3][lane32]  (M 40->48 zero-pad)

static __device__ __forceinline__ unsigned pack_h2(float lo, float hi) {
    __half2 h = __floats2half2_rn(lo, hi);
    return *reinterpret_cast<unsigned*>(&h);
}

static __device__ __forceinline__ void mma_f16(float c[4], const unsigned a[4],
                                               const unsigned b[2]) {
    asm volatile(
        "mma.sync.aligned.m16n8k16.row.col.f32.f16.f16.f32 "
        "{%0,%1,%2,%3}, {%4,%5,%6,%7}, {%8,%9}, {%0,%1,%2,%3};"
        : "+f"(c[0]), "+f"(c[1]), "+f"(c[2]), "+f"(c[3])
        : "r"(a[0]), "r"(a[1]), "r"(a[2]), "r"(a[3]), "r"(b[0]), "r"(b[1]));
}

static __device__ __forceinline__ unsigned smem_u32(const void* p) {
    return (unsigned)__cvta_generic_to_shared(p);
}
#define CP16(dst, src) \
    asm volatile("cp.async.cg.shared.global [%0], [%1], 16;" :: "r"(dst), "l"(src))
#define CP_COMMIT() asm volatile("cp.async.commit_group;")
#define CP_WAIT0()  asm volatile("cp.async.wait_group 0;")

// ---------------------------------------------------------------------------
// prep_w: pack wsc/w3/w1 into per-lane fp16 m16n8k16 A-fragments, scales folded.
// ---------------------------------------------------------------------------
__global__ void prep_w(const float* __restrict__ wsc, const float* __restrict__ w3,
                       const float* __restrict__ w1,
                       const float* __restrict__ scale_sc, const float* __restrict__ scale3,
                       const float* __restrict__ scale1)
{
    int idx = blockIdx.x * 256 + threadIdx.x;
    if (idx < 14400) {
        int lane = idx & 31; int r = idx >> 5;
        int mt = r % 10; r /= 10;
        int kt = r % 3;  r /= 3;
        int kc = r % 5;  int ct = r / 5;
        int gid = lane >> 2, tig = lane & 3;
        int row = ct * GOUT + mt * 16 + gid;
        int c0 = kc * 48 + kt * 16 + 2 * tig;
        int c2 = c0 + 8;
        float sa = scale_sc[row], sb = scale_sc[row + 8];
        const float* wr0 = wsc + (size_t)row * CIN;
        const float* wr8 = wsc + (size_t)(row + 8) * CIN;
        uint4 v;
        v.x = pack_h2(wr0[c0] * sa, wr0[c0 + 1] * sa);
        v.y = pack_h2(wr8[c0] * sb, wr8[c0 + 1] * sb);
        v.z = pack_h2(wr0[c2] * sa, wr0[c2 + 1] * sa);
        v.w = pack_h2(wr8[c2] * sb, wr8[c2 + 1] * sb);
        g_wscf[idx] = v;
    } else if (idx < 14400 + 2880) {
        int i2 = idx - 14400;
        int lane = i2 & 31; int r = i2 >> 5;
        int mt = r % 10; r /= 10;
        int kt = r % 3;  int ct = r / 3;
        int gid = lane >> 2, tig = lane & 3;
        int row = ct * GOUT + mt * 16 + gid;
        int c0 = kt * 16 + 2 * tig;
        int c2 = c0 + 8;
        float sa = scale3[row], sb = scale3[row + 8];
        const float* wr0 = w3 + (size_t)row * GMID;
        const float* wr8 = w3 + (size_t)(row + 8) * GMID;
        float e00 = (c0     < GMID) ? wr0[c0]     : 0.f;
        float e01 = (c0 + 1 < GMID) ? wr0[c0 + 1] : 0.f;
        float e80 = (c0     < GMID) ? wr8[c0]     : 0.f;
        float e81 = (c0 + 1 < GMID) ? wr8[c0 + 1] : 0.f;
        float f00 = (c2     < GMID) ? wr0[c2]     : 0.f;
        float f01 = (c2 + 1 < GMID) ? wr0[c2 + 1] : 0.f;
        float f80 = (c2     < GMID) ? wr8[c2]     : 0.f;
        float f81 = (c2 + 1 < GMID) ? wr8[c2 + 1] : 0.f;
        uint4 v;
        v.x = pack_h2(e00 * sa, e01 * sa);
        v.y = pack_h2(e80 * sb, e81 * sb);
        v.z = pack_h2(f00 * sa, f01 * sa);
        v.w = pack_h2(f80 * sb, f81 * sb);
        g_w3f[i2] = v;
    } else if (idx < 14400 + 2880 + 1440) {
        int i3 = idx - 14400 - 2880;
        int lane = i3 & 31; int r = i3 >> 5;
        int mt = r % 3; r /= 3;
        int kt = r % 5; int g = r / 5;
        int gid = lane >> 2, tig = lane & 3;
        int r0 = mt * 16 + gid;
        int r1 = r0 + 8;
        int c0 = kt * 16 + 2 * tig;
        int c2 = c0 + 8;
        float sa = (r0 < GMID) ? scale1[g * GMID + r0] : 0.f;
        float sb = (r1 < GMID) ? scale1[g * GMID + r1] : 0.f;
        const float* wr0 = w1 + ((size_t)g * GMID + r0) * GIN;
        const float* wr8 = w1 + ((size_t)g * GMID + r1) * GIN;
        uint4 v;
        v.x = pack_h2((r0 < GMID) ? wr0[c0] * sa : 0.f, (r0 < GMID) ? wr0[c0 + 1] * sa : 0.f);
        v.y = pack_h2((r1 < GMID) ? wr8[c0] * sb : 0.f, (r1 < GMID) ? wr8[c0 + 1] * sb : 0.f);
        v.z = pack_h2((r0 < GMID) ? wr0[c2] * sa : 0.f, (r0 < GMID) ? wr0[c2 + 1] * sa : 0.f);
        v.w = pack_h2((r1 < GMID) ? wr8[c2] * sb : 0.f, (r1 < GMID) ? wr8[c2 + 1] * sb : 0.f);
        g_w1f[i3] = v;
    }
}

// ---------------------------------------------------------------------------
// prep_x: convert x to fp16, packing adjacent k-pairs into half2 words.
// ---------------------------------------------------------------------------
__global__ __launch_bounds__(256) void prep_x(const float* __restrict__ x)
{
    int idx = blockIdx.x * 256 + threadIdx.x;    // NB*120*784 exactly
    int q  = idx % 784;
    int r  = idx / 784;
    int kk = r % 120, n = r / 120;
    const float4* r0 = reinterpret_cast<const float4*>(x) + ((size_t)n * CIN + 2 * kk) * 784 + q;
    const float4* r1 = r0 + 784;
    float4 a = *r0, b = *r1;
    uint4 o;
    o.x = pack_h2(a.x, b.x);
    o.y = pack_h2(a.y, b.y);
    o.z = pack_h2(a.z, b.z);
    o.w = pack_h2(a.w, b.w);
    reinterpret_cast<uint4*>(g_xh)[((size_t)n * 120 + kk) * 784 + q] = o;
}

// ---------------------------------------------------------------------------
// zero_pad: zero the 4 padded kk-rows per group in g_y2h.
// ---------------------------------------------------------------------------
__global__ __launch_bounds__(256) void zero_pad()
{
    int idx = blockIdx.x * 256 + threadIdx.x;    // NB*12*784 exactly
    int q = idx % 784;
    int r = (idx / 784) % 12;
    int n = idx / (784 * 12);
    int kk = (r >> 2) * 24 + 20 + (r & 3);
    reinterpret_cast<uint4*>(g_y2h)[((size_t)n * 72 + kk) * 784 + q] = make_uint4(0, 0, 0, 0);
}

// ---------------------------------------------------------------------------
// K1 (MMA): grouped 1x1 conv + BN(+scale folded) + ReLU -> g_y1h (fp16)
// ---------------------------------------------------------------------------
#define BROW1 72
__global__ __launch_bounds__(128) void k1_mma(const float* __restrict__ shift1)
{
    const int tile = blockIdx.x, g = blockIdx.y, n = blockIdx.z;
    const int tid = threadIdx.x, lane = tid & 31, wn = tid >> 5;
    const int gid = lane >> 2, tig = lane & 3;

    __shared__ __align__(16) uint4    s_a[480];          // 5kt x 3mt x 32
    __shared__ __align__(16) unsigned s_B[40 * BROW1];   // 40 kk-rows x 64 (+8 pad)

    {
        unsigned d = smem_u32(s_a);
        const uint4* src = g_w1f + (size_t)g * 480;
        #pragma unroll
        for (int i = tid; i < 480; i += 128)
            CP16(d + i * 16, src + i);
    }
    {
        unsigned d = smem_u32(s_B);
        const unsigned* src = g_xh + ((size_t)n * 120 + g * 40) * HW + tile * 64;
        #pragma unroll
        for (int i = tid; i < 640; i += 128) {
            int row = i >> 4, c4 = i & 15;
            CP16(d + row * (BROW1 * 4) + c4 * 16, src + (size_t)row * HW + c4 * 4);
        }
    }
    CP_COMMIT();
    CP_WAIT0();
    __syncthreads();

    float acc[3][2][4];
    #pragma unroll
    for (int mt = 0; mt < 3; mt++)
        #pragma unroll
        for (int t = 0; t < 2; t++)
            #pragma unroll
            for (int c = 0; c < 4; c++) acc[mt][t][c] = 0.f;

    #pragma unroll
    for (int kt = 0; kt < 5; kt++) {
        unsigned a[3][4];
        #pragma unroll
        for (int mt = 0; mt < 3; mt++)
            *reinterpret_cast<uint4*>(a[mt]) = s_a[(kt * 3 + mt) * 32 + lane];
        unsigned b[2][2];
        const int kb = kt * 8 + tig;
        #pragma unroll
        for (int t = 0; t < 2; t++) {
            int col = wn * 16 + t * 8 + gid;
            b[t][0] = s_B[kb * BROW1 + col];
            b[t][1] = s_B[(kb + 4) * BROW1 + col];
        }
        #pragma unroll
        for (int mt = 0; mt < 3; mt++)
            #pragma unroll
            for (int t = 0; t < 2; t++)
                mma_f16(acc[mt][t], a[mt], b[t]);
    }

    // epilogue: relu(acc + shift1) -> fp16 g_y1h
    #pragma unroll
    for (int mt = 0; mt < 3; mt++) {
        int r0 = mt * 16 + gid;
        int r1 = r0 + 8;
        int m0 = g * GMID + r0;
        float h0 = shift1[m0];
        float h1 = (r1 < GMID) ? shift1[g * GMID + r1] : 0.f;
        #pragma unroll
        for (int t = 0; t < 2; t++) {
            int px = tile * 64 + wn * 16 + t * 8 + 2 * tig;
            __half2 v0 = __floats2half2_rn(fmaxf(acc[mt][t][0] + h0, 0.f),
                                           fmaxf(acc[mt][t][1] + h0, 0.f));
            *reinterpret_cast<__half2*>(g_y1h + ((size_t)n * MID + m0) * HW + px) = v0;
            if (r1 < GMID) {
                __half2 v1 = __floats2half2_rn(fmaxf(acc[mt][t][2] + h1, 0.f),
                                               fmaxf(acc[mt][t][3] + h1, 0.f));
                *reinterpret_cast<__half2*>(g_y1h + ((size_t)n * MID + g * GMID + r1) * HW + px) = v1;
            }
        }
    }
}

// ---------------------------------------------------------------------------
// K2: depthwise 3x3 (pad 1) + BN; reads fp16 y1, two shuffled channels per
// thread, packed half2 write into g_y2h.
// ---------------------------------------------------------------------------
__global__ __launch_bounds__(256) void k2_dw(
    const float* __restrict__ w2, const float* __restrict__ scale2,
    const float* __restrict__ shift2)
{
    int idx = blockIdx.x * 256 + threadIdx.x;   // NB*60*784 threads exactly
    int q  = idx % 784;
    int r  = idx / 784;
    int kk = r % 60, n = r / 60;
    int s0 = 2 * kk, s1 = 2 * kk + 1;
    int m0 = (s0 % 3) * 40 + s0 / 3;
    int m1 = (s1 % 3) * 40 + s1 / 3;
    int w0 = (q * 4) % WW, h = (q * 4) / WW;

    float v[2][4];
    #pragma unroll
    for (int ch = 0; ch < 2; ch++) {
        int m = ch ? m1 : m0;
        const __half* p = g_y1h + ((size_t)n * MID + m) * HW + h * WW + w0;
        float l[3][6];
        #pragma unroll
        for (int rr = 0; rr < 3; rr++) {
            int hh = h - 1 + rr;
            if (hh >= 0 && hh < HH) {
                const __half* pr = p + (rr - 1) * WW;
                __half2 a = *reinterpret_cast<const __half2*>(pr);
                __half2 b = *reinterpret_cast<const __half2*>(pr + 2);
                float2 fa = __half22float2(a), fb = __half22float2(b);
                l[rr][1] = fa.x; l[rr][2] = fa.y; l[rr][3] = fb.x; l[rr][4] = fb.y;
                l[rr][0] = (w0 > 0)      ? __half2float(pr[-1]) : 0.f;
                l[rr][5] = (w0 + 4 < WW) ? __half2float(pr[4])  : 0.f;
            } else {
                #pragma unroll
                for (int j = 0; j < 6; j++) l[rr][j] = 0.f;
            }
        }
        const float* wp = w2 + m * 9;
        float wgt[9];
        #pragma unroll
        for (int i = 0; i < 9; i++) wgt[i] = wp[i];
        float sc = scale2[m], sh = shift2[m];
        #pragma unroll
        for (int j = 0; j < 4; j++) {
            float a = 0.f;
            #pragma unroll
            for (int rr = 0; rr < 3; rr++)
                #pragma unroll
                for (int d = 0; d < 3; d++)
                    a = fmaf(wgt[rr * 3 + d], l[rr][j + d], a);
            v[ch][j] = fmaf(a, sc, sh);
        }
    }

    int row = (s0 / 40) * 24 + (s0 % 40) / 2;
    uint4 o;
    o.x = pack_h2(v[0][0], v[1][0]);
    o.y = pack_h2(v[0][1], v[1][1]);
    o.z = pack_h2(v[0][2], v[1][2]);
    o.w = pack_h2(v[0][3], v[1][3]);
    reinterpret_cast<uint4*>(g_y2h)[((size_t)n * 72 + row) * 784 + q] = o;
}

// ---------------------------------------------------------------------------
// K3: fp16 m16n8k16 MMA. 128 thr, warp grid 2m x 2n (warp tile 80 rows x 32 px:
// squarer tile -> 41% fewer fragment L1 wavefronts). K chunks of 48 (3 kt).
// A frags + B half2 tiles cp.async double-buffered. 3 CTAs/SM target.
// ---------------------------------------------------------------------------
#define AW_ELEMS 960
#define BROW 72
#define BWORDS (24 * BROW)
#define SMEM_K3 (2 * AW_ELEMS * 16 + 2 * BWORDS * 4)

static __device__ __forceinline__ void cp_A(uint4* __restrict__ dst,
                                            const uint4* __restrict__ src, int tid)
{
    unsigned d = smem_u32(dst);
    #pragma unroll
    for (int i = tid; i < AW_ELEMS; i += 128)
        CP16(d + i * 16, src + i);
}

static __device__ __forceinline__ void cp_B(unsigned* __restrict__ dst,
                                            const unsigned* __restrict__ src, int tid)
{
    unsigned d = smem_u32(dst);
    #pragma unroll
    for (int i = tid; i < 384; i += 128) {
        int row = i >> 4, c4 = i & 15;
        CP16(d + row * (BROW * 4) + c4 * 16, src + (size_t)row * HW + c4 * 4);
    }
}

static __device__ __forceinline__ void compute_chunk(
    const uint4* __restrict__ aw, const unsigned* __restrict__ sB,
    int wm, int wn, int lane, float acc[5][4][4])
{
    const int gid = lane >> 2, tig = lane & 3;
    #pragma unroll
    for (int kt = 0; kt < 3; kt++) {
        unsigned a[5][4];
        #pragma unroll
        for (int j = 0; j < 5; j++)
            *reinterpret_cast<uint4*>(a[j]) = aw[(kt * 10 + wm * 5 + j) * 32 + lane];
        unsigned b[4][2];
        const int kb = kt * 8 + tig;
        #pragma unroll
        for (int t = 0; t < 4; t++) {
            int col = wn * 32 + t * 8 + gid;
            b[t][0] = sB[kb * BROW + col];
            b[t][1] = sB[(kb + 4) * BROW + col];
        }
        #pragma unroll
        for (int j = 0; j < 5; j++)
            #pragma unroll
            for (int t = 0; t < 4; t++)
                mma_f16(acc[j][t], a[j], b[t]);
    }
}

__global__ __launch_bounds__(128, 3) void k3_fused(
    const float* __restrict__ shift3, const float* __restrict__ shift_sc,
    float* __restrict__ out)
{
    const int tile = blockIdx.x, ct = blockIdx.y, n = blockIdx.z;
    const int tid = threadIdx.x, lane = tid & 31, warp = tid >> 5;
    const int wm = warp & 1;           // m half (80 rows)
    const int wn = warp >> 1;          // 32-px half
    const int gid = lane >> 2, tig = lane & 3;

    extern __shared__ __align__(16) char smem[];
    uint4*    s_aw = reinterpret_cast<uint4*>(smem);
    unsigned* s_B  = reinterpret_cast<unsigned*>(smem + 2 * AW_ELEMS * 16);

    float acc[5][4][4];
    #pragma unroll
    for (int j = 0; j < 5; j++)
        #pragma unroll
        for (int t = 0; t < 4; t++)
            #pragma unroll
            for (int c = 0; c < 4; c++) acc[j][t][c] = 0.f;

    const uint4* a_src[6];
    const unsigned* b_src[6];
    a_src[0] = g_w3f + (size_t)ct * 960;
    b_src[0] = g_y2h + ((size_t)n * 72 + ct * 24) * HW + tile * 64;
    #pragma unroll
    for (int kc = 0; kc < 5; kc++) {
        a_src[1 + kc] = g_wscf + (size_t)(ct * 5 + kc) * 960;
        b_src[1 + kc] = g_xh + ((size_t)n * 120 + kc * 24) * HW + tile * 64;
    }

    cp_A(s_aw, a_src[0], tid);
    cp_B(s_B, b_src[0], tid);
    CP_COMMIT();

    #pragma unroll 1
    for (int c = 0; c < 6; c++) {
        int cb = c & 1;
        CP_WAIT0();
        __syncthreads();
        if (c < 5) {
            cp_A(s_aw + ((c + 1) & 1) * AW_ELEMS, a_src[c + 1], tid);
            cp_B(s_B + ((c + 1) & 1) * BWORDS, b_src[c + 1], tid);
            CP_COMMIT();
        }
        compute_chunk(s_aw + cb * AW_ELEMS, s_B + cb * BWORDS, wm, wn, lane, acc);
        if (c == 0) {
            // acc := relu(acc + shift3) + shift_sc ; shortcut accumulates on top
            #pragma unroll
            for (int j = 0; j < 5; j++) {
                int rb = ct * GOUT + wm * 80 + j * 16;
                int r0 = rb + gid, r1 = r0 + 8;
                float h3a = shift3[r0], hsa = shift_sc[r0];
                float h3b = shift3[r1], hsb = shift_sc[r1];
                #pragma unroll
                for (int t = 0; t < 4; t++) {
                    acc[j][t][0] = fmaxf(acc[j][t][0] + h3a, 0.f) + hsa;
                    acc[j][t][1] = fmaxf(acc[j][t][1] + h3a, 0.f) + hsa;
                    acc[j][t][2] = fmaxf(acc[j][t][2] + h3b, 0.f) + hsb;
                    acc[j][t][3] = fmaxf(acc[j][t][3] + h3b, 0.f) + hsb;
                }
            }
        }
        __syncthreads();
    }

    // epilogue
    #pragma unroll
    for (int j = 0; j < 5; j++) {
        int rb = ct * GOUT + wm * 80 + j * 16;
        int r0 = rb + gid, r1 = r0 + 8;
        #pragma unroll
        for (int t = 0; t < 4; t++) {
            int px = tile * 64 + wn * 32 + t * 8 + 2 * tig;
            float2 v0, v1;
            v0.x = acc[j][t][0]; v0.y = acc[j][t][1];
            v1.x = acc[j][t][2]; v1.y = acc[j][t][3];
            *reinterpret_cast<float2*>(out + ((size_t)n * COUT + r0) * HW + px) = v0;
            *reinterpret_cast<float2*>(out + ((size_t)n * COUT + r1) * HW + px) = v1;
        }
    }
}

// ---------------------------------------------------------------------------
extern "C" void kernel_launch(void* const* d_in, const int* in_sizes, int n_in,
                              void* d_out, int out_size)
{
    const float* x        = (const float*)d_in[0];
    const float* w1       = (const float*)d_in[1];
    const float* scale1   = (const float*)d_in[2];
    const float* shift1   = (const float*)d_in[3];
    const float* w2       = (const float*)d_in[4];
    const float* scale2   = (const float*)d_in[5];
    const float* shift2   = (const float*)d_in[6];
    const float* w3       = (const float*)d_in[7];
    const float* scale3   = (const float*)d_in[8];
    const float* shift3   = (const float*)d_in[9];
    const float* wsc      = (const float*)d_in[10];
    const float* scale_sc = (const float*)d_in[11];
    const float* shift_sc = (const float*)d_in[12];
    float* out = (float*)d_out;

    cudaFuncSetAttribute(k3_fused, cudaFuncAttributeMaxDynamicSharedMemorySize, SMEM_K3);

    prep_w<<<(14400 + 2880 + 1440 + 255) / 256, 256>>>(wsc, w3, w1, scale_sc, scale3, scale1);
    prep_x<<<(NB * 120 * 784) / 256, 256>>>(x);
    zero_pad<<<(NB * 12 * 784) / 256, 256>>>();
    k1_mma<<<dim3(49, 3, NB), 128>>>(shift1);
    k2_dw<<<(NB * 60 * 784) / 256, 256>>>(w2, scale2, shift2);
    k3_fused<<<dim3(49, 3, NB), 128, SMEM_K3>>>(shift3, shift_sc, out);
}

// round 14
// speedup vs baseline: 1.2017x; 1.0022x over previous
#include <cuda_runtime.h>
#include <cuda_fp16.h>

#define NB   32
#define CIN  240
#define HH   56
#define WW   56
#define HW   3136
#define MID  120
#define COUT 480
#define GRP  3
#define GIN  80    // Cin / G
#define GMID 40    // mid / G
#define GOUT 160   // Cout / G

// Scratch (allocation-free rule: __device__ globals).
// g_xh / g_y2h padded +64 words: K3's 128-px tail tile reads up to 63 words OOB.
__device__ __half   g_y1h[NB * MID * HW];         // conv1 output (post BN+ReLU), fp16 planar
__device__ unsigned g_xh[NB * 120 * HW + 64];     // x as k-pair-packed half2 words
__device__ unsigned g_y2h[NB * 72 * HW + 64];     // dw out, SHUFFLED, half2, 24 rows/group (20+4 zero)
// Pre-packed fp16 A-fragments (mma.m16n8k16 per-lane layout), BN scale FOLDED IN
__device__ uint4 g_wscf[14400];   // wsc*scale_sc: [ct3][kc5][kt3][mt10][lane32]
__device__ uint4 g_w3f[2880];     // w3*scale3:    [ct3][kt3][mt10][lane32] (K 40->48 zero-pad)
__device__ uint4 g_w1f[1440];     // w1*scale1:    [g3][kt5][mt3][lane32]  (M 40->48 zero-pad)

static __device__ __forceinline__ unsigned pack_h2(float lo, float hi) {
    __half2 h = __floats2half2_rn(lo, hi);
    return *reinterpret_cast<unsigned*>(&h);
}

static __device__ __forceinline__ void mma_f16(float c[4], const unsigned a[4],
                                               const unsigned b[2]) {
    asm volatile(
        "mma.sync.aligned.m16n8k16.row.col.f32.f16.f16.f32 "
        "{%0,%1,%2,%3}, {%4,%5,%6,%7}, {%8,%9}, {%0,%1,%2,%3};"
        : "+f"(c[0]), "+f"(c[1]), "+f"(c[2]), "+f"(c[3])
        : "r"(a[0]), "r"(a[1]), "r"(a[2]), "r"(a[3]), "r"(b[0]), "r"(b[1]));
}

static __device__ __forceinline__ unsigned smem_u32(const void* p) {
    return (unsigned)__cvta_generic_to_shared(p);
}
#define CP16(dst, src) \
    asm volatile("cp.async.cg.shared.global [%0], [%1], 16;" :: "r"(dst), "l"(src))
#define CP_COMMIT() asm volatile("cp.async.commit_group;")
#define CP_WAIT0()  asm volatile("cp.async.wait_group 0;")

// ---------------------------------------------------------------------------
// prep_w: pack wsc/w3/w1 into per-lane fp16 m16n8k16 A-fragments, scales folded.
// ---------------------------------------------------------------------------
__global__ void prep_w(const float* __restrict__ wsc, const float* __restrict__ w3,
                       const float* __restrict__ w1,
                       const float* __restrict__ scale_sc, const float* __restrict__ scale3,
                       const float* __restrict__ scale1)
{
    int idx = blockIdx.x * 256 + threadIdx.x;
    if (idx < 14400) {
        int lane = idx & 31; int r = idx >> 5;
        int mt = r % 10; r /= 10;
        int kt = r % 3;  r /= 3;
        int kc = r % 5;  int ct = r / 5;
        int gid = lane >> 2, tig = lane & 3;
        int row = ct * GOUT + mt * 16 + gid;
        int c0 = kc * 48 + kt * 16 + 2 * tig;
        int c2 = c0 + 8;
        float sa = scale_sc[row], sb = scale_sc[row + 8];
        const float* wr0 = wsc + (size_t)row * CIN;
        const float* wr8 = wsc + (size_t)(row + 8) * CIN;
        uint4 v;
        v.x = pack_h2(wr0[c0] * sa, wr0[c0 + 1] * sa);
        v.y = pack_h2(wr8[c0] * sb, wr8[c0 + 1] * sb);
        v.z = pack_h2(wr0[c2] * sa, wr0[c2 + 1] * sa);
        v.w = pack_h2(wr8[c2] * sb, wr8[c2 + 1] * sb);
        g_wscf[idx] = v;
    } else if (idx < 14400 + 2880) {
        int i2 = idx - 14400;
        int lane = i2 & 31; int r = i2 >> 5;
        int mt = r % 10; r /= 10;
        int kt = r % 3;  int ct = r / 3;
        int gid = lane >> 2, tig = lane & 3;
        int row = ct * GOUT + mt * 16 + gid;
        int c0 = kt * 16 + 2 * tig;
        int c2 = c0 + 8;
        float sa = scale3[row], sb = scale3[row + 8];
        const float* wr0 = w3 + (size_t)row * GMID;
        const float* wr8 = w3 + (size_t)(row + 8) * GMID;
        float e00 = (c0     < GMID) ? wr0[c0]     : 0.f;
        float e01 = (c0 + 1 < GMID) ? wr0[c0 + 1] : 0.f;
        float e80 = (c0     < GMID) ? wr8[c0]     : 0.f;
        float e81 = (c0 + 1 < GMID) ? wr8[c0 + 1] : 0.f;
        float f00 = (c2     < GMID) ? wr0[c2]     : 0.f;
        float f01 = (c2 + 1 < GMID) ? wr0[c2 + 1] : 0.f;
        float f80 = (c2     < GMID) ? wr8[c2]     : 0.f;
        float f81 = (c2 + 1 < GMID) ? wr8[c2 + 1] : 0.f;
        uint4 v;
        v.x = pack_h2(e00 * sa, e01 * sa);
        v.y = pack_h2(e80 * sb, e81 * sb);
        v.z = pack_h2(f00 * sa, f01 * sa);
        v.w = pack_h2(f80 * sb, f81 * sb);
        g_w3f[i2] = v;
    } else if (idx < 14400 + 2880 + 1440) {
        int i3 = idx - 14400 - 2880;
        int lane = i3 & 31; int r = i3 >> 5;
        int mt = r % 3; r /= 3;
        int kt = r % 5; int g = r / 5;
        int gid = lane >> 2, tig = lane & 3;
        int r0 = mt * 16 + gid;
        int r1 = r0 + 8;
        int c0 = kt * 16 + 2 * tig;
        int c2 = c0 + 8;
        float sa = (r0 < GMID) ? scale1[g * GMID + r0] : 0.f;
        float sb = (r1 < GMID) ? scale1[g * GMID + r1] : 0.f;
        const float* wr0 = w1 + ((size_t)g * GMID + r0) * GIN;
        const float* wr8 = w1 + ((size_t)g * GMID + r1) * GIN;
        uint4 v;
        v.x = pack_h2((r0 < GMID) ? wr0[c0] * sa : 0.f, (r0 < GMID) ? wr0[c0 + 1] * sa : 0.f);
        v.y = pack_h2((r1 < GMID) ? wr8[c0] * sb : 0.f, (r1 < GMID) ? wr8[c0 + 1] * sb : 0.f);
        v.z = pack_h2((r0 < GMID) ? wr0[c2] * sa : 0.f, (r0 < GMID) ? wr0[c2 + 1] * sa : 0.f);
        v.w = pack_h2((r1 < GMID) ? wr8[c2] * sb : 0.f, (r1 < GMID) ? wr8[c2 + 1] * sb : 0.f);
        g_w1f[i3] = v;
    }
}

// ---------------------------------------------------------------------------
// prep_x: convert x to fp16, packing adjacent k-pairs into half2 words.
// ---------------------------------------------------------------------------
__global__ __launch_bounds__(256) void prep_x(const float* __restrict__ x)
{
    int idx = blockIdx.x * 256 + threadIdx.x;    // NB*120*784 exactly
    int q  = idx % 784;
    int r  = idx / 784;
    int kk = r % 120, n = r / 120;
    const float4* r0 = reinterpret_cast<const float4*>(x) + ((size_t)n * CIN + 2 * kk) * 784 + q;
    const float4* r1 = r0 + 784;
    float4 a = *r0, b = *r1;
    uint4 o;
    o.x = pack_h2(a.x, b.x);
    o.y = pack_h2(a.y, b.y);
    o.z = pack_h2(a.z, b.z);
    o.w = pack_h2(a.w, b.w);
    reinterpret_cast<uint4*>(g_xh)[((size_t)n * 120 + kk) * 784 + q] = o;
}

// ---------------------------------------------------------------------------
// zero_pad: zero the 4 padded kk-rows per group in g_y2h.
// ---------------------------------------------------------------------------
__global__ __launch_bounds__(256) void zero_pad()
{
    int idx = blockIdx.x * 256 + threadIdx.x;    // NB*12*784 exactly
    int q = idx % 784;
    int r = (idx / 784) % 12;
    int n = idx / (784 * 12);
    int kk = (r >> 2) * 24 + 20 + (r & 3);
    reinterpret_cast<uint4*>(g_y2h)[((size_t)n * 72 + kk) * 784 + q] = make_uint4(0, 0, 0, 0);
}

// ---------------------------------------------------------------------------
// K1 (MMA): grouped 1x1 conv + BN(+scale folded) + ReLU -> g_y1h (fp16)
// ---------------------------------------------------------------------------
#define BROW1 72
__global__ __launch_bounds__(128) void k1_mma(const float* __restrict__ shift1)
{
    const int tile = blockIdx.x, g = blockIdx.y, n = blockIdx.z;
    const int tid = threadIdx.x, lane = tid & 31, wn = tid >> 5;
    const int gid = lane >> 2, tig = lane & 3;

    __shared__ __align__(16) uint4    s_a[480];          // 5kt x 3mt x 32
    __shared__ __align__(16) unsigned s_B[40 * BROW1];   // 40 kk-rows x 64 (+8 pad)

    {
        unsigned d = smem_u32(s_a);
        const uint4* src = g_w1f + (size_t)g * 480;
        #pragma unroll
        for (int i = tid; i < 480; i += 128)
            CP16(d + i * 16, src + i);
    }
    {
        unsigned d = smem_u32(s_B);
        const unsigned* src = g_xh + ((size_t)n * 120 + g * 40) * HW + tile * 64;
        #pragma unroll
        for (int i = tid; i < 640; i += 128) {
            int row = i >> 4, c4 = i & 15;
            CP16(d + row * (BROW1 * 4) + c4 * 16, src + (size_t)row * HW + c4 * 4);
        }
    }
    CP_COMMIT();
    CP_WAIT0();
    __syncthreads();

    float acc[3][2][4];
    #pragma unroll
    for (int mt = 0; mt < 3; mt++)
        #pragma unroll
        for (int t = 0; t < 2; t++)
            #pragma unroll
            for (int c = 0; c < 4; c++) acc[mt][t][c] = 0.f;

    #pragma unroll
    for (int kt = 0; kt < 5; kt++) {
        unsigned a[3][4];
        #pragma unroll
        for (int mt = 0; mt < 3; mt++)
            *reinterpret_cast<uint4*>(a[mt]) = s_a[(kt * 3 + mt) * 32 + lane];
        unsigned b[2][2];
        const int kb = kt * 8 + tig;
        #pragma unroll
        for (int t = 0; t < 2; t++) {
            int col = wn * 16 + t * 8 + gid;
            b[t][0] = s_B[kb * BROW1 + col];
            b[t][1] = s_B[(kb + 4) * BROW1 + col];
        }
        #pragma unroll
        for (int mt = 0; mt < 3; mt++)
            #pragma unroll
            for (int t = 0; t < 2; t++)
                mma_f16(acc[mt][t], a[mt], b[t]);
    }

    // epilogue: relu(acc + shift1) -> fp16 g_y1h
    #pragma unroll
    for (int mt = 0; mt < 3; mt++) {
        int r0 = mt * 16 + gid;
        int r1 = r0 + 8;
        int m0 = g * GMID + r0;
        float h0 = shift1[m0];
        float h1 = (r1 < GMID) ? shift1[g * GMID + r1] : 0.f;
        #pragma unroll
        for (int t = 0; t < 2; t++) {
            int px = tile * 64 + wn * 16 + t * 8 + 2 * tig;
            __half2 v0 = __floats2half2_rn(fmaxf(acc[mt][t][0] + h0, 0.f),
                                           fmaxf(acc[mt][t][1] + h0, 0.f));
            *reinterpret_cast<__half2*>(g_y1h + ((size_t)n * MID + m0) * HW + px) = v0;
            if (r1 < GMID) {
                __half2 v1 = __floats2half2_rn(fmaxf(acc[mt][t][2] + h1, 0.f),
                                               fmaxf(acc[mt][t][3] + h1, 0.f));
                *reinterpret_cast<__half2*>(g_y1h + ((size_t)n * MID + g * GMID + r1) * HW + px) = v1;
            }
        }
    }
}

// ---------------------------------------------------------------------------
// K2: depthwise 3x3 (pad 1) + BN; 8 px per thread (uint4 + 2 scalar halo per
// row per ch), two shuffled channels, packed half2 write into g_y2h.
// ---------------------------------------------------------------------------
__global__ __launch_bounds__(256) void k2_dw(
    const float* __restrict__ w2, const float* __restrict__ scale2,
    const float* __restrict__ shift2)
{
    int idx = blockIdx.x * 256 + threadIdx.x;   // NB*60*392 threads exactly
    int s  = idx % 392;
    int r  = idx / 392;
    int kk = r % 60, n = r / 60;
    int s0 = 2 * kk, s1 = 2 * kk + 1;
    int m0 = (s0 % 3) * 40 + s0 / 3;
    int m1 = (s1 % 3) * 40 + s1 / 3;
    int wseg = s % 7, h = s / 7;
    int w0 = wseg * 8;

    float v[2][8];
    #pragma unroll
    for (int ch = 0; ch < 2; ch++) {
        int m = ch ? m1 : m0;
        const __half* p = g_y1h + ((size_t)n * MID + m) * HW + h * WW + w0;
        float l[3][10];
        #pragma unroll
        for (int rr = 0; rr < 3; rr++) {
            int hh = h - 1 + rr;
            if (hh >= 0 && hh < HH) {
                const __half* pr = p + (rr - 1) * WW;
                uint4 c = *reinterpret_cast<const uint4*>(pr);   // 8 halves
                const __half2* ph = reinterpret_cast<const __half2*>(&c);
                #pragma unroll
                for (int q2 = 0; q2 < 4; q2++) {
                    float2 f = __half22float2(ph[q2]);
                    l[rr][1 + 2 * q2] = f.x;
                    l[rr][2 + 2 * q2] = f.y;
                }
                l[rr][0] = (w0 > 0)      ? __half2float(pr[-1]) : 0.f;
                l[rr][9] = (w0 + 8 < WW) ? __half2float(pr[8])  : 0.f;
            } else {
                #pragma unroll
                for (int j = 0; j < 10; j++) l[rr][j] = 0.f;
            }
        }
        const float* wp = w2 + m * 9;
        float wgt[9];
        #pragma unroll
        for (int i = 0; i < 9; i++) wgt[i] = wp[i];
        float sc = scale2[m], sh = shift2[m];
        #pragma unroll
        for (int j = 0; j < 8; j++) {
            float a = 0.f;
            #pragma unroll
            for (int rr = 0; rr < 3; rr++)
                #pragma unroll
                for (int d = 0; d < 3; d++)
                    a = fmaf(wgt[rr * 3 + d], l[rr][j + d], a);
            v[ch][j] = fmaf(a, sc, sh);
        }
    }

    int row = (s0 / 40) * 24 + (s0 % 40) / 2;
    unsigned* dst = g_y2h + ((size_t)n * 72 + row) * HW + h * WW + w0;
    uint4 oA, oB;
    oA.x = pack_h2(v[0][0], v[1][0]);
    oA.y = pack_h2(v[0][1], v[1][1]);
    oA.z = pack_h2(v[0][2], v[1][2]);
    oA.w = pack_h2(v[0][3], v[1][3]);
    oB.x = pack_h2(v[0][4], v[1][4]);
    oB.y = pack_h2(v[0][5], v[1][5]);
    oB.z = pack_h2(v[0][6], v[1][6]);
    oB.w = pack_h2(v[0][7], v[1][7]);
    *reinterpret_cast<uint4*>(dst)     = oA;
    *reinterpret_cast<uint4*>(dst + 4) = oB;
}

// ---------------------------------------------------------------------------
// K3: fp16 m16n8k16 MMA. 256 thr, N=128 px per CTA (25 tiles, tail guarded),
// warp grid 2m x 4n, warp tile 80x32. K chunks of 48 (3 kt), double-buffered.
// ---------------------------------------------------------------------------
#define AW_ELEMS 960
#define BROW 136                                     // 128 half2 words + 8 pad
#define BWORDS (24 * BROW)                           // 3264
#define SMEM_K3 (2 * AW_ELEMS * 16 + 2 * BWORDS * 4) // 30720 + 26112 = 56832

static __device__ __forceinline__ void cp_A(uint4* __restrict__ dst,
                                            const uint4* __restrict__ src, int tid)
{
    unsigned d = smem_u32(dst);
    #pragma unroll
    for (int i = tid; i < AW_ELEMS; i += 256)
        CP16(d + i * 16, src + i);
}

// B tile: 24 kk-rows x 128 half2 (32 x 16B granules per row)
static __device__ __forceinline__ void cp_B(unsigned* __restrict__ dst,
                                            const unsigned* __restrict__ src, int tid)
{
    unsigned d = smem_u32(dst);
    #pragma unroll
    for (int i = tid; i < 768; i += 256) {
        int row = i >> 5, c4 = i & 31;
        CP16(d + (row * BROW + c4 * 4) * 4, src + (size_t)row * HW + c4 * 4);
    }
}

static __device__ __forceinline__ void compute_chunk(
    const uint4* __restrict__ aw, const unsigned* __restrict__ sB,
    int wm, int wn, int lane, float acc[5][4][4])
{
    const int gid = lane >> 2, tig = lane & 3;
    #pragma unroll
    for (int kt = 0; kt < 3; kt++) {
        unsigned a[5][4];
        #pragma unroll
        for (int j = 0; j < 5; j++)
            *reinterpret_cast<uint4*>(a[j]) = aw[(kt * 10 + wm * 5 + j) * 32 + lane];
        unsigned b[4][2];
        const int kb = kt * 8 + tig;
        #pragma unroll
        for (int t = 0; t < 4; t++) {
            int col = wn * 32 + t * 8 + gid;
            b[t][0] = sB[kb * BROW + col];
            b[t][1] = sB[(kb + 4) * BROW + col];
        }
        #pragma unroll
        for (int j = 0; j < 5; j++)
            #pragma unroll
            for (int t = 0; t < 4; t++)
                mma_f16(acc[j][t], a[j], b[t]);
    }
}

__global__ __launch_bounds__(256, 2) void k3_fused(
    const float* __restrict__ shift3, const float* __restrict__ shift_sc,
    float* __restrict__ out)
{
    const int tile = blockIdx.x, ct = blockIdx.y, n = blockIdx.z;
    const int tid = threadIdx.x, lane = tid & 31, warp = tid >> 5;
    const int wm = warp & 1;           // m half (80 rows)
    const int wn = warp >> 1;          // 32-px strip (0..3)
    const int gid = lane >> 2, tig = lane & 3;

    extern __shared__ __align__(16) char smem[];
    uint4*    s_aw = reinterpret_cast<uint4*>(smem);
    unsigned* s_B  = reinterpret_cast<unsigned*>(smem + 2 * AW_ELEMS * 16);

    float acc[5][4][4];
    #pragma unroll
    for (int j = 0; j < 5; j++)
        #pragma unroll
        for (int t = 0; t < 4; t++)
            #pragma unroll
            for (int c = 0; c < 4; c++) acc[j][t][c] = 0.f;

    const uint4* a_src[6];
    const unsigned* b_src[6];
    a_src[0] = g_w3f + (size_t)ct * 960;
    b_src[0] = g_y2h + ((size_t)n * 72 + ct * 24) * HW + tile * 128;
    #pragma unroll
    for (int kc = 0; kc < 5; kc++) {
        a_src[1 + kc] = g_wscf + (size_t)(ct * 5 + kc) * 960;
        b_src[1 + kc] = g_xh + ((size_t)n * 120 + kc * 24) * HW + tile * 128;
    }

    cp_A(s_aw, a_src[0], tid);
    cp_B(s_B, b_src[0], tid);
    CP_COMMIT();

    #pragma unroll 1
    for (int c = 0; c < 6; c++) {
        int cb = c & 1;
        CP_WAIT0();
        __syncthreads();
        if (c < 5) {
            cp_A(s_aw + ((c + 1) & 1) * AW_ELEMS, a_src[c + 1], tid);
            cp_B(s_B + ((c + 1) & 1) * BWORDS, b_src[c + 1], tid);
            CP_COMMIT();
        }
        compute_chunk(s_aw + cb * AW_ELEMS, s_B + cb * BWORDS, wm, wn, lane, acc);
        if (c == 0) {
            // acc := relu(acc + shift3) + shift_sc ; shortcut accumulates on top
            #pragma unroll
            for (int j = 0; j < 5; j++) {
                int rb = ct * GOUT + wm * 80 + j * 16;
                int r0 = rb + gid, r1 = r0 + 8;
                float h3a = shift3[r0], hsa = shift_sc[r0];
                float h3b = shift3[r1], hsb = shift_sc[r1];
                #pragma unroll
                for (int t = 0; t < 4; t++) {
                    acc[j][t][0] = fmaxf(acc[j][t][0] + h3a, 0.f) + hsa;
                    acc[j][t][1] = fmaxf(acc[j][t][1] + h3a, 0.f) + hsa;
                    acc[j][t][2] = fmaxf(acc[j][t][2] + h3b, 0.f) + hsb;
                    acc[j][t][3] = fmaxf(acc[j][t][3] + h3b, 0.f) + hsb;
                }
            }
        }
        __syncthreads();
    }

    // epilogue (guard the half-valid tail tile)
    #pragma unroll
    for (int j = 0; j < 5; j++) {
        int rb = ct * GOUT + wm * 80 + j * 16;
        int r0 = rb + gid, r1 = r0 + 8;
        #pragma unroll
        for (int t = 0; t < 4; t++) {
            int px = tile * 128 + wn * 32 + t * 8 + 2 * tig;
            if (px < HW) {
                float2 v0, v1;
                v0.x = acc[j][t][0]; v0.y = acc[j][t][1];
                v1.x = acc[j][t][2]; v1.y = acc[j][t][3];
                *reinterpret_cast<float2*>(out + ((size_t)n * COUT + r0) * HW + px) = v0;
                *reinterpret_cast<float2*>(out + ((size_t)n * COUT + r1) * HW + px) = v1;
            }
        }
    }
}

// ---------------------------------------------------------------------------
extern "C" void kernel_launch(void* const* d_in, const int* in_sizes, int n_in,
                              void* d_out, int out_size)
{
    const float* x        = (const float*)d_in[0];
    const float* w1       = (const float*)d_in[1];
    const float* scale1   = (const float*)d_in[2];
    const float* shift1   = (const float*)d_in[3];
    const float* w2       = (const float*)d_in[4];
    const float* scale2   = (const float*)d_in[5];
    const float* shift2   = (const float*)d_in[6];
    const float* w3       = (const float*)d_in[7];
    const float* scale3   = (const float*)d_in[8];
    const float* shift3   = (const float*)d_in[9];
    const float* wsc      = (const float*)d_in[10];
    const float* scale_sc = (const float*)d_in[11];
    const float* shift_sc = (const float*)d_in[12];
    float* out = (float*)d_out;

    cudaFuncSetAttribute(k3_fused, cudaFuncAttributeMaxDynamicSharedMemorySize, SMEM_K3);

    prep_w<<<(14400 + 2880 + 1440 + 255) / 256, 256>>>(wsc, w3, w1, scale_sc, scale3, scale1);
    prep_x<<<(NB * 120 * 784) / 256, 256>>>(x);
    zero_pad<<<(NB * 12 * 784) / 256, 256>>>();
    k1_mma<<<dim3(49, 3, NB), 128>>>(shift1);
    k2_dw<<<(NB * 60 * 392) / 256, 256>>>(w2, scale2, shift2);
    k3_fused<<<dim3(25, 3, NB), 256, SMEM_K3>>>(shift3, shift_sc, out);
}